// round 16
// baseline (speedup 1.0000x reference)
#include <cuda_runtime.h>
#include <cuda_fp16.h>
#include <math.h>
#include <cstdint>

#define DD 512
#define MAXM 100064
#define PV 64
#define FCAP 40000

// ---------------- scratch ----------------
__device__ __align__(16) float g_bufA[(size_t)MAXM * DD];
__device__ __align__(16) float g_bufB[(size_t)MAXM * DD];
__device__ __align__(16) float g_srcb[(size_t)MAXM * 64];
__device__ __align__(16) float g_dstT[64 * 64];
__device__ __align__(16) float g_tail1[PV * DD];   // exact tail h1 scratch; reused as T
__device__ __align__(16) float g_tail2[PV * DD];
__device__ int g_cmap[MAXM];
__device__ int g_list[FCAP];
__device__ int g_cnt;

// pre-split weight fragment buffers (hi/lo fp16, mma B-fragment layout)
__device__ __align__(16) uint2 g_Winh[65536],  g_Winl[65536];
__device__ __align__(16) uint2 g_Wench[65536], g_Wencl[65536];
__device__ __align__(16) uint2 g_Wagh[65536],  g_Wagl[65536];
__device__ __align__(16) uint2 g_Wouth[65536], g_Woutl[65536];
__device__ __align__(16) uint2 g_Wsh[8192],    g_Wsl[8192];

__device__ __forceinline__ float elu1(float x) { return x > 0.f ? x : expm1f(x); }

// ---------------- all-weight pre-split into fragment layout (single launch) -------------
__device__ __forceinline__ void do_presplit(const float* W, int ld, int idx,
                                            uint2* Bh, uint2* Bl)
{
    int lane = idx & 31;
    int ks = (idx >> 5) & 1;
    int rest = idx >> 6;
    int c = rest & 15;          // KC = 16
    int ntg = rest >> 4;
    int row = ntg * 8 + (lane >> 2);
    int k0 = c * 32 + ks * 16 + (lane & 3) * 2;
    const float* wr = W + (size_t)row * ld;
    float a0 = wr[k0], a1 = wr[k0 + 1], a2 = wr[k0 + 8], a3 = wr[k0 + 9];
    __half h0 = __float2half_rn(a0), h1 = __float2half_rn(a1);
    __half h2 = __float2half_rn(a2), h3 = __float2half_rn(a3);
    __half2 H0 = __halves2half2(h0, h1), H1 = __halves2half2(h2, h3);
    __half2 L0 = __floats2half2_rn(a0 - __half2float(h0), a1 - __half2float(h1));
    __half2 L1 = __floats2half2_rn(a2 - __half2float(h2), a3 - __half2float(h3));
    Bh[idx] = make_uint2(*reinterpret_cast<unsigned*>(&H0), *reinterpret_cast<unsigned*>(&H1));
    Bl[idx] = make_uint2(*reinterpret_cast<unsigned*>(&L0), *reinterpret_cast<unsigned*>(&L1));
}

__global__ void presplit_all_k(const float* __restrict__ Win, const float* __restrict__ Wenc,
                               const float* __restrict__ Wag, const float* __restrict__ Wout,
                               const float* __restrict__ Ws)
{
    int idx = blockIdx.x * blockDim.x + threadIdx.x;
    if (idx < 65536)           do_presplit(Win,  DD,   idx,           g_Winh,  g_Winl);
    else if (idx < 131072)     do_presplit(Wenc, DD,   idx - 65536,   g_Wench, g_Wencl);
    else if (idx < 196608)     do_presplit(Wag,  2*DD, idx - 131072,  g_Wagh,  g_Wagl);
    else if (idx < 262144)     do_presplit(Wout, DD,   idx - 196608,  g_Wouth, g_Woutl);
    else if (idx < 270336)     do_presplit(Ws,   DD,   idx - 262144,  g_Wsh,   g_Wsl);
}

// ======================================================================================
// fp32 FFMA SGEMM — ascending-k fmaf chain per element, bit-identical across configs.
// ======================================================================================
template<int BM,int BN,int BK,int TM,int TN>
__global__ void sgemm_k(const float* __restrict__ A,
                        const float* __restrict__ B, const float* __restrict__ bias,
                        float* __restrict__ C,
                        int M, int Nc, int K, const int* __restrict__ Mp, int Bld)
{
    constexpr int THREADS = (BM/TM)*(BN/TN);
    __shared__ float As[BK][BM];
    __shared__ float Bs[BK][BN];

    if (Mp) { M = *Mp; if (M > FCAP) M = FCAP; }
    const int bm = blockIdx.y * BM;
    if (bm >= M) return;
    const int tid = threadIdx.x;
    const int bn = blockIdx.x * BN;
    const int tx = tid % (BN/TN);
    const int ty = tid / (BN/TN);

    float acc[TM][TN];
    #pragma unroll
    for (int i = 0; i < TM; i++)
        #pragma unroll
        for (int j = 0; j < TN; j++) acc[i][j] = 0.f;

    constexpr int A_IT = (BM*BK/4) / THREADS;
    constexpr int B_IT = (BN*BK/4) / THREADS;

    for (int k0 = 0; k0 < K; k0 += BK) {
        #pragma unroll
        for (int it = 0; it < A_IT; it++) {
            int id = tid + it*THREADS;
            int r  = id / (BK/4);
            int c4 = id % (BK/4);
            int grow = bm + r;
            int rr = grow < M ? grow : M-1;
            int gk = k0 + c4*4;
            float4 v = *reinterpret_cast<const float4*>(A + (size_t)rr*K + gk);
            As[c4*4+0][r] = v.x; As[c4*4+1][r] = v.y;
            As[c4*4+2][r] = v.z; As[c4*4+3][r] = v.w;
        }
        #pragma unroll
        for (int it = 0; it < B_IT; it++) {
            int id = tid + it*THREADS;
            int r  = id / (BK/4);
            int c4 = id % (BK/4);
            float4 v = *reinterpret_cast<const float4*>(B + (size_t)(bn + r)*Bld + k0 + c4*4);
            Bs[c4*4+0][r] = v.x; Bs[c4*4+1][r] = v.y;
            Bs[c4*4+2][r] = v.z; Bs[c4*4+3][r] = v.w;
        }
        __syncthreads();

        #pragma unroll
        for (int k = 0; k < BK; k++) {
            float ra[TM], rb[TN];
            #pragma unroll
            for (int i = 0; i < TM; i += 4) {
                if (TM >= 4) {
                    float4 v = *reinterpret_cast<const float4*>(&As[k][ty*TM + i]);
                    ra[i]=v.x; ra[i+1]=v.y; ra[i+2]=v.z; ra[i+3]=v.w;
                } else {
                    #pragma unroll
                    for (int u = 0; u < TM; u++) ra[u] = As[k][ty*TM + u];
                }
            }
            #pragma unroll
            for (int j = 0; j < TN; j += 4) {
                if (TN >= 4) {
                    float4 v = *reinterpret_cast<const float4*>(&Bs[k][tx*TN + j]);
                    rb[j]=v.x; rb[j+1]=v.y; rb[j+2]=v.z; rb[j+3]=v.w;
                } else {
                    #pragma unroll
                    for (int u = 0; u < TN; u++) rb[u] = Bs[k][tx*TN + u];
                }
            }
            #pragma unroll
            for (int i = 0; i < TM; i++)
                #pragma unroll
                for (int j = 0; j < TN; j++)
                    acc[i][j] = fmaf(ra[i], rb[j], acc[i][j]);
        }
        __syncthreads();
    }

    #pragma unroll
    for (int i = 0; i < TM; i++) {
        int row = bm + ty*TM + i;
        if (row >= M) continue;
        #pragma unroll
        for (int j = 0; j < TN; j++) {
            int col = bn + tx*TN + j;
            C[(size_t)row*Nc + col] = acc[i][j] + bias[col];
        }
    }
}

// ======================================================================================
// HMMA fp16 2-way-split (3 products) GEMM — round-12 base + fragment double-buffering:
// both ks fragment sets loaded before the mma burst (LDS latency hidden).
// ======================================================================================
__device__ __forceinline__ void split4(float4 v, unsigned& h0, unsigned& h1,
                                       unsigned& l0, unsigned& l1) {
    __half hx = __float2half_rn(v.x), hy = __float2half_rn(v.y);
    __half hz = __float2half_rn(v.z), hw = __float2half_rn(v.w);
    __half2 H0 = __halves2half2(hx, hy), H1 = __halves2half2(hz, hw);
    float lx = v.x - __half2float(hx), ly = v.y - __half2float(hy);
    float lz = v.z - __half2float(hz), lw = v.w - __half2float(hw);
    __half2 L0 = __floats2half2_rn(lx, ly), L1 = __floats2half2_rn(lz, lw);
    h0 = *reinterpret_cast<unsigned*>(&H0); h1 = *reinterpret_cast<unsigned*>(&H1);
    l0 = *reinterpret_cast<unsigned*>(&L0); l1 = *reinterpret_cast<unsigned*>(&L1);
}

__device__ __forceinline__ void mma16816(float* d, const unsigned* a, const unsigned* b) {
    asm("mma.sync.aligned.m16n8k16.row.col.f32.f16.f16.f32 "
        "{%0,%1,%2,%3}, {%4,%5,%6,%7}, {%8,%9}, {%0,%1,%2,%3};"
        : "+f"(d[0]), "+f"(d[1]), "+f"(d[2]), "+f"(d[3])
        : "r"(a[0]), "r"(a[1]), "r"(a[2]), "r"(a[3]), "r"(b[0]), "r"(b[1]));
}

// AMODE: 0 plain / 1 vnode-substitute tail.  SMODE: 0 / 1 split C,C2.
// EMODE: 0 += bias[col] / 1 += rowT[map[row]*512 + col].
template<int BN, int AMODE, int SMODE, int EMODE>
__global__ void __launch_bounds__(256, 1) hgemm_k(
    const float* __restrict__ A, const float* __restrict__ A2, const int* __restrict__ map,
    const uint2* __restrict__ Bhg, const uint2* __restrict__ Blg,
    const float* __restrict__ bias, const float* __restrict__ rowT,
    float* __restrict__ C, float* __restrict__ C2,
    int M, int Nc, int K, int Nsplit)
{
    extern __shared__ char sm[];
    constexpr int NT = 4;
    constexpr int WN = BN / 32;
    constexpr int WM = 8 / WN;
    constexpr int MT = 128 / (WM * 16);
    constexpr int ASZ = 8192;
    constexpr int BOFF = 2 * ASZ;
    constexpr int BSZ = BN * 64;
    constexpr int STAGE = 2 * ASZ + 2 * BSZ;
    constexpr int B_IT = BN / 32;

    const int tid = threadIdx.x;
    const int wid = tid >> 5, lane = tid & 31;
    const int grp = lane >> 2, tig = lane & 3;
    const int bm = blockIdx.y * 128, bn = blockIdx.x * BN;
    const int wm = wid / WN, wn = wid % WN;
    const int KC = K >> 5;
    const int ntg_cta0 = bn >> 3;

    float acc[MT][NT][4];
    #pragma unroll
    for (int i = 0; i < MT; i++)
        #pragma unroll
        for (int j = 0; j < NT; j++)
            #pragma unroll
            for (int q = 0; q < 4; q++) acc[i][j][q] = 0.f;

    float4 ra[4];
    uint2 rbh[B_IT], rbl[B_IT];

    auto loadA = [&](int k0) {
        #pragma unroll
        for (int it = 0; it < 4; it++) {
            int id = tid + it * 256;
            int r = id >> 3, q = id & 7;
            int rr = bm + r; if (rr >= M) rr = M - 1;
            int gk = k0 + q * 4;
            const float* p;
            if (AMODE == 0) p = A + (size_t)rr * K + gk;
            else            p = ((rr < Nsplit) ? A + (size_t)rr * K
                                               : A2 + (size_t)(rr - Nsplit) * K) + gk;
            ra[it] = *reinterpret_cast<const float4*>(p);
        }
    };

    auto loadB = [&](int c) {
        #pragma unroll
        for (int it = 0; it < B_IT; it++) {
            int l = tid + it * 256;
            int ntg_local = l >> 6, rem = l & 63;
            int gidx = ((ntg_cta0 + ntg_local) * KC + c) * 64 + rem;
            rbh[it] = __ldg(Bhg + gidx);
            rbl[it] = __ldg(Blg + gidx);
        }
    };

    auto storeStage = [&](char* stg) {
        #pragma unroll
        for (int it = 0; it < 4; it++) {
            int id = tid + it * 256;
            int r = id >> 3, q = id & 7;
            int kc = q * 4, ks = kc >> 4, kcw = kc & 15;
            int mt = r >> 4;
            int lane0 = (r & 7) * 4 + ((kcw & 7) >> 1);
            int reg = ((r >> 3) & 1) + ((kcw >> 3) << 1);
            unsigned h0, h1, l0, l1; split4(ra[it], h0, h1, l0, l1);
            unsigned off = ((ks * 8 + mt) * 32 + lane0) * 16 + reg * 4;
            *reinterpret_cast<unsigned*>(stg + off) = h0;
            *reinterpret_cast<unsigned*>(stg + off + 16) = h1;
            *reinterpret_cast<unsigned*>(stg + ASZ + off) = l0;
            *reinterpret_cast<unsigned*>(stg + ASZ + off + 16) = l1;
        }
        #pragma unroll
        for (int it = 0; it < B_IT; it++) {
            int l = tid + it * 256;
            *reinterpret_cast<uint2*>(stg + BOFF + l * 8) = rbh[it];
            *reinterpret_cast<uint2*>(stg + BOFF + BSZ + l * 8) = rbl[it];
        }
    };

    // fragment registers: both ks sets resident
    unsigned Ah[2][MT][4], Al[2][MT][4], Bh[2][NT][2], Bl[2][NT][2];

    auto loadFrag = [&](const char* stg, int ks, int s) {
        #pragma unroll
        for (int t = 0; t < NT; t++) {
            int l = (wn * NT + t) * 64 + ks * 32 + lane;
            uint2 h = *reinterpret_cast<const uint2*>(stg + BOFF + l * 8);
            uint2 lo = *reinterpret_cast<const uint2*>(stg + BOFF + BSZ + l * 8);
            Bh[s][t][0] = h.x; Bh[s][t][1] = h.y;
            Bl[s][t][0] = lo.x; Bl[s][t][1] = lo.y;
        }
        #pragma unroll
        for (int t = 0; t < MT; t++) {
            int mt = wm * MT + t;
            unsigned off = ((ks * 8 + mt) * 32 + lane) * 16;
            uint4 h = *reinterpret_cast<const uint4*>(stg + off);
            uint4 l = *reinterpret_cast<const uint4*>(stg + ASZ + off);
            Ah[s][t][0] = h.x; Ah[s][t][1] = h.y; Ah[s][t][2] = h.z; Ah[s][t][3] = h.w;
            Al[s][t][0] = l.x; Al[s][t][1] = l.y; Al[s][t][2] = l.z; Al[s][t][3] = l.w;
        }
    };

    loadA(0); loadB(0);
    storeStage(sm);
    __syncthreads();

    const int NCH = KC;
    for (int i = 0; i < NCH; i++) {
        char* stg = sm + (i & 1) * STAGE;
        loadFrag(stg, 0, 0);                                   // frag ks=0 (LDS in flight)
        if (i + 1 < NCH) { loadA((i + 1) * 32); loadB(i + 1); } // global prefetch overlaps
        loadFrag(stg, 1, 1);                                   // frag ks=1
        #pragma unroll
        for (int s = 0; s < 2; s++)
            #pragma unroll
            for (int ti = 0; ti < MT; ti++)
                #pragma unroll
                for (int tj = 0; tj < NT; tj++) {
                    mma16816(acc[ti][tj], Ah[s][ti], Bh[s][tj]);
                    mma16816(acc[ti][tj], Ah[s][ti], Bl[s][tj]);
                    mma16816(acc[ti][tj], Al[s][ti], Bh[s][tj]);
                }
        if (i + 1 < NCH) {
            storeStage(sm + ((i + 1) & 1) * STAGE);
            __syncthreads();
        }
    }

    #pragma unroll
    for (int i = 0; i < MT; i++) {
        #pragma unroll
        for (int j = 0; j < NT; j++) {
            int col = bn + (wn * NT + j) * 8 + tig * 2;
            float bx = 0.f, by = 0.f;
            if (EMODE == 0) { bx = bias[col]; by = bias[col + 1]; }
            int row0 = bm + (wm * MT + i) * 16 + grp;
            #pragma unroll
            for (int h = 0; h < 2; h++) {
                int row = row0 + h * 8;
                if (row >= M) continue;
                float ax = acc[i][j][h * 2 + 0];
                float ay = acc[i][j][h * 2 + 1];
                float2 v;
                if (EMODE == 1) {
                    const float* tb = rowT + (size_t)map[row] * DD + col;
                    v = make_float2(ax + tb[0], ay + tb[1]);
                } else {
                    v = make_float2(ax + bx, ay + by);
                }
                if (SMODE == 0 || row < Nsplit) {
                    *reinterpret_cast<float2*>(C + (size_t)row * Nc + col) = v;
                } else {
                    float* p = C2 + (size_t)(row - Nsplit) * Nc + col;
                    p[0] = v.x; p[1] = v.y;
                }
            }
        }
    }
}

// ---------------- fused LayerNorm + ELU (+ optional tail bias), warp/row ----------------
__global__ void ln_elu_k(const float* __restrict__ in, float* __restrict__ out,
                         const float* __restrict__ g, const float* __restrict__ beta,
                         const float* __restrict__ tail_bias, int M, int Ntail0)
{
    int w = (blockIdx.x * blockDim.x + threadIdx.x) >> 5;
    int lane = threadIdx.x & 31;
    if (w >= M) return;
    const float* row = in + (size_t)w * DD;
    float4 v[4];
    float s = 0.f, sq = 0.f;
    #pragma unroll
    for (int q = 0; q < 4; q++) {
        v[q] = *reinterpret_cast<const float4*>(row + q * 128 + lane * 4);
        s  += v[q].x + v[q].y + v[q].z + v[q].w;
        sq += v[q].x * v[q].x + v[q].y * v[q].y + v[q].z * v[q].z + v[q].w * v[q].w;
    }
    #pragma unroll
    for (int o = 16; o; o >>= 1) {
        s  += __shfl_xor_sync(0xffffffffu, s,  o);
        sq += __shfl_xor_sync(0xffffffffu, sq, o);
    }
    float mean = s * (1.f / 512.f);
    float var  = sq * (1.f / 512.f) - mean * mean;
    float inv  = rsqrtf(var + 1e-5f);
    float* orow = out + (size_t)w * DD;
    bool tail = (tail_bias != nullptr) && (w >= Ntail0);
    #pragma unroll
    for (int q = 0; q < 4; q++) {
        int c = q * 128 + lane * 4;
        float4 gv = *reinterpret_cast<const float4*>(g + c);
        float4 bv = *reinterpret_cast<const float4*>(beta + c);
        float4 o;
        o.x = elu1((v[q].x - mean) * inv * gv.x + bv.x);
        o.y = elu1((v[q].y - mean) * inv * gv.y + bv.y);
        o.z = elu1((v[q].z - mean) * inv * gv.z + bv.z);
        o.w = elu1((v[q].w - mean) * inv * gv.w + bv.w);
        if (tail) {
            float4 tb = *reinterpret_cast<const float4*>(tail_bias + (size_t)(w - Ntail0) * DD + c);
            o.x += tb.x; o.y += tb.y; o.z += tb.z; o.w += tb.w;
        }
        *reinterpret_cast<float4*>(orow + c) = o;
    }
}

// ---------------- exact LN+ELU on compact rows (verbatim ln_elu arithmetic) --------------
__global__ void ln_fix_k(const float* __restrict__ in, float* __restrict__ out,
                         const float* __restrict__ g, const float* __restrict__ beta,
                         const float* __restrict__ tb, const int* __restrict__ cntp, int nfix)
{
    int n = cntp ? *cntp : nfix;
    if (n > FCAP) n = FCAP;
    int nw = (gridDim.x * blockDim.x) >> 5;
    int gw = (blockIdx.x * blockDim.x + threadIdx.x) >> 5;
    int lane = threadIdx.x & 31;
    for (int w = gw; w < n; w += nw) {
        const float* row = in + (size_t)w * DD;
        float4 v[4];
        float s = 0.f, sq = 0.f;
        #pragma unroll
        for (int q = 0; q < 4; q++) {
            v[q] = *reinterpret_cast<const float4*>(row + q * 128 + lane * 4);
            s  += v[q].x + v[q].y + v[q].z + v[q].w;
            sq += v[q].x * v[q].x + v[q].y * v[q].y + v[q].z * v[q].z + v[q].w * v[q].w;
        }
        #pragma unroll
        for (int o = 16; o; o >>= 1) {
            s  += __shfl_xor_sync(0xffffffffu, s,  o);
            sq += __shfl_xor_sync(0xffffffffu, sq, o);
        }
        float mean = s * (1.f / 512.f);
        float var  = sq * (1.f / 512.f) - mean * mean;
        float inv  = rsqrtf(var + 1e-5f);
        float* orow = out + (size_t)w * DD;
        bool tail = (tb != nullptr);
        #pragma unroll
        for (int q = 0; q < 4; q++) {
            int c = q * 128 + lane * 4;
            float4 gv = *reinterpret_cast<const float4*>(g + c);
            float4 bv = *reinterpret_cast<const float4*>(beta + c);
            float4 o;
            o.x = elu1((v[q].x - mean) * inv * gv.x + bv.x);
            o.y = elu1((v[q].y - mean) * inv * gv.y + bv.y);
            o.z = elu1((v[q].z - mean) * inv * gv.z + bv.z);
            o.w = elu1((v[q].w - mean) * inv * gv.w + bv.w);
            if (tail) {
                float4 t = *reinterpret_cast<const float4*>(tb + (size_t)w * DD + c);
                o.x += t.x; o.y += t.y; o.z += t.z; o.w += t.w;
            }
            *reinterpret_cast<float4*>(orow + c) = o;
        }
    }
}

// ---------------- dst[64,64] = h_tail @ Wd^T + bd + attn_bias, transposed ---------------
__global__ void dst_k(const float* __restrict__ h_tail, const float* __restrict__ Wd,
                      const float* __restrict__ bd, const float* __restrict__ ab,
                      float* __restrict__ dstT)
{
    int idx = blockIdx.x * blockDim.x + threadIdx.x;
    if (idx >= 64 * 64) return;
    int j = idx >> 6;
    int a = idx & 63;
    const float* hr = h_tail + (size_t)j * DD;
    const float* wr = Wd + (size_t)a * DD;
    float s = 0.f;
    for (int d = 0; d < DD; d += 4) {
        float4 hv = *reinterpret_cast<const float4*>(hr + d);
        float4 wv = *reinterpret_cast<const float4*>(wr + d);
        s = fmaf(hv.x, wv.x, s); s = fmaf(hv.y, wv.y, s);
        s = fmaf(hv.z, wv.z, s); s = fmaf(hv.w, wv.w, s);
    }
    s += bd[a] + ab[j * 64 + a];
    dstT[a * 64 + j] = s;
}

// ---------------- argmax + ambiguity flagging ----------------
__global__ void argmax_flag_k(const float* __restrict__ src, const float* __restrict__ dstT,
                              int* __restrict__ cmap, float* __restrict__ map_out,
                              int* __restrict__ list, int* __restrict__ cnt, int Nrows)
{
    __shared__ float sdT[64 * 64];
    __shared__ float ssrc[8][64];
    int tid = threadIdx.x;
    for (int i = tid; i < 64 * 64; i += blockDim.x) sdT[i] = dstT[i];
    __syncthreads();
    int warp = tid >> 5, lane = tid & 31;
    int row0 = blockIdx.x * 64;
    for (int r = warp; r < 64; r += 8) {
        int row = row0 + r;
        if (row >= Nrows) break;
        ssrc[warp][lane]      = src[(size_t)row * 64 + lane];
        ssrc[warp][lane + 32] = src[(size_t)row * 64 + lane + 32];
        __syncwarp();
        float a = 0.f, b = 0.f;
        #pragma unroll
        for (int k = 0; k < 64; k++) {
            float sv = ssrc[warp][k];
            a = fmaf(sv, sdT[k * 64 + lane],      a);
            b = fmaf(sv, sdT[k * 64 + lane + 32], b);
        }
        float v1, v2; int i1;
        if (b > a) { v1 = b; i1 = lane + 32; v2 = a; }
        else       { v1 = a; i1 = lane;      v2 = b; }
        #pragma unroll
        for (int o = 16; o; o >>= 1) {
            float ov1 = __shfl_xor_sync(0xffffffffu, v1, o);
            int   oi1 = __shfl_xor_sync(0xffffffffu, i1, o);
            float ov2 = __shfl_xor_sync(0xffffffffu, v2, o);
            if (ov1 > v1 || (ov1 == v1 && oi1 < i1)) {
                v2 = fmaxf(v1, ov2); v1 = ov1; i1 = oi1;
            } else {
                v2 = fmaxf(ov1, v2);
            }
        }
        if (lane == 0) {
            cmap[row] = i1; map_out[row] = (float)i1;
            if (v1 - v2 < 1e-4f * (1.f + fabsf(v1))) {
                int ix = atomicAdd(cnt, 1);
                if (ix < FCAP) list[ix] = row;
            }
        }
        __syncwarp();
    }
}

// ---------------- gather flagged x rows into compact buffer ----------------
__global__ void gather_k(const float* __restrict__ x, const int* __restrict__ list,
                         const int* __restrict__ cntp, float* __restrict__ out)
{
    int n = *cntp; if (n > FCAP) n = FCAP;
    for (int i = blockIdx.x; i < n; i += gridDim.x) {
        int row = list[i];
        const float4* s = reinterpret_cast<const float4*>(x + (size_t)row * DD);
        float4* d = reinterpret_cast<float4*>(out + (size_t)i * DD);
        for (int k = threadIdx.x; k < DD / 4; k += blockDim.x) d[k] = s[k];
    }
}

// ---------------- exact rescore + argmax for flagged rows ----------------
__global__ void rescore_k(const float* __restrict__ h2, const float* __restrict__ Ws,
                          const float* __restrict__ bs, const float* __restrict__ dstT,
                          const int* __restrict__ list, const int* __restrict__ cntp,
                          int* __restrict__ cmap, float* __restrict__ map_out)
{
    __shared__ float sdT[64 * 64];
    __shared__ float ssrc[8][64];
    int tid = threadIdx.x;
    for (int i = tid; i < 64 * 64; i += blockDim.x) sdT[i] = dstT[i];
    __syncthreads();
    int warp = tid >> 5, lane = tid & 31;
    int n = *cntp; if (n > FCAP) n = FCAP;
    int nw = gridDim.x * 8;
    for (int i = blockIdx.x * 8 + warp; i < n; i += nw) {
        const float4* hr = reinterpret_cast<const float4*>(h2 + (size_t)i * DD);
        #pragma unroll
        for (int half = 0; half < 2; half++) {
            int a = lane + half * 32;
            const float4* w = reinterpret_cast<const float4*>(Ws + (size_t)a * DD);
            float acc = 0.f;
            for (int k = 0; k < DD / 4; k++) {
                float4 h = hr[k]; float4 ww = w[k];
                acc = fmaf(h.x, ww.x, acc); acc = fmaf(h.y, ww.y, acc);
                acc = fmaf(h.z, ww.z, acc); acc = fmaf(h.w, ww.w, acc);
            }
            ssrc[warp][a] = acc + bs[a];
        }
        __syncwarp();
        float a = 0.f, b = 0.f;
        #pragma unroll
        for (int k = 0; k < 64; k++) {
            float sv = ssrc[warp][k];
            a = fmaf(sv, sdT[k * 64 + lane],      a);
            b = fmaf(sv, sdT[k * 64 + lane + 32], b);
        }
        float bv; int bi;
        if (b > a) { bv = b; bi = lane + 32; } else { bv = a; bi = lane; }
        #pragma unroll
        for (int o = 16; o; o >>= 1) {
            float ov = __shfl_xor_sync(0xffffffffu, bv, o);
            int   oi = __shfl_xor_sync(0xffffffffu, bi, o);
            if (ov > bv || (ov == bv && oi < bi)) { bv = ov; bi = oi; }
        }
        if (lane == 0) { int row = list[i]; cmap[row] = bi; map_out[row] = (float)bi; }
        __syncwarp();
    }
}

// ---------------- misc ----------------
__global__ void zero_k() { g_cnt = 0; }

__global__ void tail_setup_k(float* __restrict__ h, const float* __restrict__ vbd,
                             int* __restrict__ cmap, float* __restrict__ lossp, int Ntail0)
{
    int idx = blockIdx.x * blockDim.x + threadIdx.x;
    if (idx < PV * DD) h[(size_t)Ntail0 * DD + idx] += vbd[idx];
    if (idx < PV) cmap[Ntail0 + idx] = idx;
    if (idx == 0) *lossp = 0.f;
}

extern "C" void kernel_launch(void* const* d_in, const int* in_sizes, int n_in,
                              void* d_out, int out_size)
{
    const float* x    = (const float*)d_in[0];
    const float* vemb = (const float*)d_in[1];
    const float* vbh  = (const float*)d_in[2];
    const float* vbd  = (const float*)d_in[3];
    const float* Win  = (const float*)d_in[4];
    const float* bin  = (const float*)d_in[5];
    const float* ghid = (const float*)d_in[6];
    const float* bhid = (const float*)d_in[7];
    const float* Wenc = (const float*)d_in[8];
    const float* benc = (const float*)d_in[9];
    const float* gdcd = (const float*)d_in[10];
    const float* bdcd = (const float*)d_in[11];
    const float* Ws   = (const float*)d_in[12];
    const float* bs   = (const float*)d_in[13];
    const float* Wd   = (const float*)d_in[14];
    const float* bd   = (const float*)d_in[15];
    const float* ab   = (const float*)d_in[16];
    const float* Wag  = (const float*)d_in[17];
    const float* bag  = (const float*)d_in[18];
    const float* Wout = (const float*)d_in[19];
    const float* bout = (const float*)d_in[20];

    const int M = in_sizes[0] / DD;
    const int N = M - PV;

    float *bufA, *bufB, *srcb, *dstT, *tail1, *tail2; int *cmap, *list, *cnt;
    uint2 *Winh, *Winl, *Wench, *Wencl, *Wagh, *Wagl, *Wouth, *Woutl, *Wsh, *Wsl;
    cudaGetSymbolAddress((void**)&bufA, g_bufA);
    cudaGetSymbolAddress((void**)&bufB, g_bufB);
    cudaGetSymbolAddress((void**)&srcb, g_srcb);
    cudaGetSymbolAddress((void**)&dstT, g_dstT);
    cudaGetSymbolAddress((void**)&tail1, g_tail1);
    cudaGetSymbolAddress((void**)&tail2, g_tail2);
    cudaGetSymbolAddress((void**)&cmap, g_cmap);
    cudaGetSymbolAddress((void**)&list, g_list);
    cudaGetSymbolAddress((void**)&cnt, g_cnt);
    cudaGetSymbolAddress((void**)&Winh, g_Winh);   cudaGetSymbolAddress((void**)&Winl, g_Winl);
    cudaGetSymbolAddress((void**)&Wench, g_Wench); cudaGetSymbolAddress((void**)&Wencl, g_Wencl);
    cudaGetSymbolAddress((void**)&Wagh, g_Wagh);   cudaGetSymbolAddress((void**)&Wagl, g_Wagl);
    cudaGetSymbolAddress((void**)&Wouth, g_Wouth); cudaGetSymbolAddress((void**)&Woutl, g_Woutl);
    cudaGetSymbolAddress((void**)&Wsh, g_Wsh);     cudaGetSymbolAddress((void**)&Wsl, g_Wsl);

    float* out   = (float*)d_out;
    float* lossp = out + (size_t)N * DD;
    float* reps  = lossp + 1;
    float* mapo  = reps + (size_t)PV * DD;

    float* xg = bufA;
    float* t1 = bufA + (size_t)FCAP * DD;
    float* t2 = bufA;
    float* Tb = tail1;   // T table (64 x 512)

    constexpr int SMH   = 2 * (2 * 8192 + 2 * 128 * 64);  // 65536 (BN=128)
    constexpr int SMH64 = 2 * (2 * 8192 + 2 * 64 * 64);   // 49152 (BN=64)
    cudaFuncSetAttribute(hgemm_k<128,1,0,0>, cudaFuncAttributeMaxDynamicSharedMemorySize, SMH);
    cudaFuncSetAttribute(hgemm_k<128,0,0,0>, cudaFuncAttributeMaxDynamicSharedMemorySize, SMH);
    cudaFuncSetAttribute(hgemm_k<128,0,0,1>, cudaFuncAttributeMaxDynamicSharedMemorySize, SMH);
    cudaFuncSetAttribute(hgemm_k<128,0,1,0>, cudaFuncAttributeMaxDynamicSharedMemorySize, SMH);
    cudaFuncSetAttribute(hgemm_k<64,0,0,0>,  cudaFuncAttributeMaxDynamicSharedMemorySize, SMH64);

    const int gm = (M + 127) / 128;
    const dim3 gfix(8, (FCAP + 63) / 64);
    dim3 blk(256);

    zero_k<<<1, 1>>>();

    // ---- all weight pre-splits in ONE launch ----
    presplit_all_k<<<(270336 + 255) / 256, 256>>>(Win, Wenc, Wag, Wout, Ws);

    // ---- GEMM1 (HMMA) + LN ; exact tail h1 (32x32 tile, bit-identical chain) ----
    hgemm_k<128,1,0,0><<<dim3(DD/128, gm), blk, SMH>>>(x, vemb, nullptr, Winh, Winl, bin, nullptr, bufA, nullptr, M, DD, DD, N);
    ln_elu_k<<<(M + 7) / 8, 256>>>(bufA, bufB, ghid, bhid, vbh, M, N);
    sgemm_k<32,32,64,2,2><<<dim3(16, 2), blk>>>(vemb, Win, bin, tail1, PV, DD, DD, nullptr, DD);
    ln_fix_k<<<8, 256>>>(tail1, bufB + (size_t)N * DD, ghid, bhid, vbh, nullptr, PV);

    // ---- GEMM2 (HMMA) + LN ; exact tail h2 ----
    hgemm_k<128,0,0,0><<<dim3(DD/128, gm), blk, SMH>>>(bufB, nullptr, nullptr, Wench, Wencl, benc, nullptr, bufA, nullptr, M, DD, DD, N);
    sgemm_k<32,32,64,2,2><<<dim3(16, 2), blk>>>(bufB + (size_t)N * DD, Wenc, benc, tail2, PV, DD, DD, nullptr, DD);
    ln_elu_k<<<(M + 7) / 8, 256>>>(bufA, bufB, gdcd, bdcd, nullptr, M, N);
    ln_fix_k<<<8, 256>>>(tail2, bufB + (size_t)N * DD, gdcd, bdcd, nullptr, nullptr, PV);

    // ---- src (HMMA) ; dst (exact) ; argmax+flag ----
    hgemm_k<64,0,0,0><<<dim3(1, (N + 127) / 128), blk, SMH64>>>(bufB, nullptr, nullptr, Wsh, Wsl, bs, nullptr, srcb, nullptr, N, 64, DD, N);
    dst_k<<<16, 256>>>(bufB + (size_t)N * DD, Wd, bd, ab, dstT);
    argmax_flag_k<<<(N + 63) / 64, 256>>>(srcb, dstT, cmap, mapo, list, cnt, N);

    // ---- exact repair of flagged rows ----
    gather_k<<<2048, 128>>>(x, list, cnt, xg);
    sgemm_k<64,64,64,4,4><<<gfix, blk>>>(xg, Win, bin, t1, 0, DD, DD, cnt, DD);
    ln_fix_k<<<512, 256>>>(t1, t1, ghid, bhid, nullptr, cnt, 0);
    sgemm_k<64,64,64,4,4><<<gfix, blk>>>(t1, Wenc, benc, t2, 0, DD, DD, cnt, DD);
    ln_fix_k<<<512, 256>>>(t2, t2, gdcd, bdcd, nullptr, cnt, 0);
    rescore_k<<<256, 256>>>(t2, Ws, bs, dstT, list, cnt, cmap, mapo);

    // ---- tail fixups ----
    tail_setup_k<<<(PV * DD + 255) / 256, 256>>>(bufB, vbd, cmap, lossp, N);

    // ---- T table: T[j] = h_tail'[j] @ WagRight^T + bag ----
    sgemm_k<32,32,64,2,2><<<dim3(16, 2), blk>>>(bufB + (size_t)N * DD, Wag + 512, bag, Tb, PV, DD, DD, nullptr, 2*DD);

    // ---- aggr (HMMA, K=512 + per-row T epilogue) ; LN ; out (HMMA, split store) ----
    hgemm_k<128,0,0,1><<<dim3(DD/128, gm), blk, SMH>>>(bufB, nullptr, cmap, Wagh, Wagl, bag, Tb, bufA, nullptr, M, DD, DD, N);
    ln_elu_k<<<(M + 7) / 8, 256>>>(bufA, bufB, gdcd, bdcd, nullptr, M, N);
    hgemm_k<128,0,1,0><<<dim3(DD/128, gm), blk, SMH>>>(bufB, nullptr, nullptr, Wouth, Woutl, bout, nullptr, out, reps, M, DD, DD, N);
}

// round 17
// speedup vs baseline: 1.5194x; 1.5194x over previous
#include <cuda_runtime.h>
#include <cuda_fp16.h>
#include <math.h>
#include <cstdint>

#define DD 512
#define MAXM 100064
#define PV 64
#define FCAP 40000

// ---------------- scratch ----------------
__device__ __align__(16) float g_bufA[(size_t)MAXM * DD];
__device__ __align__(16) float g_bufB[(size_t)MAXM * DD];
__device__ __align__(16) float g_srcb[(size_t)MAXM * 64];
__device__ __align__(16) float g_dstT[64 * 64];
__device__ __align__(16) float g_tail1[PV * DD];   // exact tail h1 scratch; reused as T
__device__ __align__(16) float g_tail2[PV * DD];
__device__ int g_cmap[MAXM];
__device__ int g_list[FCAP];
__device__ int g_cnt;

// pre-split weight fragment buffers (hi/lo fp16, mma B-fragment layout)
__device__ __align__(16) uint2 g_Winh[65536],  g_Winl[65536];
__device__ __align__(16) uint2 g_Wench[65536], g_Wencl[65536];
__device__ __align__(16) uint2 g_Wagh[65536],  g_Wagl[65536];
__device__ __align__(16) uint2 g_Wouth[65536], g_Woutl[65536];
__device__ __align__(16) uint2 g_Wsh[8192],    g_Wsl[8192];

__device__ __forceinline__ float elu1(float x) { return x > 0.f ? x : expm1f(x); }

// ---------------- all-weight pre-split into fragment layout (single launch) -------------
__device__ __forceinline__ void do_presplit(const float* W, int ld, int idx,
                                            uint2* Bh, uint2* Bl)
{
    int lane = idx & 31;
    int ks = (idx >> 5) & 1;
    int rest = idx >> 6;
    int c = rest & 15;          // KC = 16
    int ntg = rest >> 4;
    int row = ntg * 8 + (lane >> 2);
    int k0 = c * 32 + ks * 16 + (lane & 3) * 2;
    const float* wr = W + (size_t)row * ld;
    float a0 = wr[k0], a1 = wr[k0 + 1], a2 = wr[k0 + 8], a3 = wr[k0 + 9];
    __half h0 = __float2half_rn(a0), h1 = __float2half_rn(a1);
    __half h2 = __float2half_rn(a2), h3 = __float2half_rn(a3);
    __half2 H0 = __halves2half2(h0, h1), H1 = __halves2half2(h2, h3);
    __half2 L0 = __floats2half2_rn(a0 - __half2float(h0), a1 - __half2float(h1));
    __half2 L1 = __floats2half2_rn(a2 - __half2float(h2), a3 - __half2float(h3));
    Bh[idx] = make_uint2(*reinterpret_cast<unsigned*>(&H0), *reinterpret_cast<unsigned*>(&H1));
    Bl[idx] = make_uint2(*reinterpret_cast<unsigned*>(&L0), *reinterpret_cast<unsigned*>(&L1));
}

__global__ void presplit_all_k(const float* __restrict__ Win, const float* __restrict__ Wenc,
                               const float* __restrict__ Wag, const float* __restrict__ Wout,
                               const float* __restrict__ Ws)
{
    int idx = blockIdx.x * blockDim.x + threadIdx.x;
    if (idx < 65536)           do_presplit(Win,  DD,   idx,           g_Winh,  g_Winl);
    else if (idx < 131072)     do_presplit(Wenc, DD,   idx - 65536,   g_Wench, g_Wencl);
    else if (idx < 196608)     do_presplit(Wag,  2*DD, idx - 131072,  g_Wagh,  g_Wagl);
    else if (idx < 262144)     do_presplit(Wout, DD,   idx - 196608,  g_Wouth, g_Woutl);
    else if (idx < 270336)     do_presplit(Ws,   DD,   idx - 262144,  g_Wsh,   g_Wsl);
    else if (idx == 270336)    g_cnt = 0;
}

// ======================================================================================
// fp32 FFMA SGEMM — ascending-k fmaf chain per element, bit-identical across configs.
// ======================================================================================
template<int BM,int BN,int BK,int TM,int TN>
__global__ void sgemm_k(const float* __restrict__ A,
                        const float* __restrict__ B, const float* __restrict__ bias,
                        float* __restrict__ C,
                        int M, int Nc, int K, const int* __restrict__ Mp, int Bld)
{
    constexpr int THREADS = (BM/TM)*(BN/TN);
    __shared__ float As[BK][BM];
    __shared__ float Bs[BK][BN];

    if (Mp) { M = *Mp; if (M > FCAP) M = FCAP; }
    const int bm = blockIdx.y * BM;
    if (bm >= M) return;
    const int tid = threadIdx.x;
    const int bn = blockIdx.x * BN;
    const int tx = tid % (BN/TN);
    const int ty = tid / (BN/TN);

    float acc[TM][TN];
    #pragma unroll
    for (int i = 0; i < TM; i++)
        #pragma unroll
        for (int j = 0; j < TN; j++) acc[i][j] = 0.f;

    constexpr int A_IT = (BM*BK/4) / THREADS;
    constexpr int B_IT = (BN*BK/4) / THREADS;

    for (int k0 = 0; k0 < K; k0 += BK) {
        #pragma unroll
        for (int it = 0; it < A_IT; it++) {
            int id = tid + it*THREADS;
            int r  = id / (BK/4);
            int c4 = id % (BK/4);
            int grow = bm + r;
            int rr = grow < M ? grow : M-1;
            int gk = k0 + c4*4;
            float4 v = *reinterpret_cast<const float4*>(A + (size_t)rr*K + gk);
            As[c4*4+0][r] = v.x; As[c4*4+1][r] = v.y;
            As[c4*4+2][r] = v.z; As[c4*4+3][r] = v.w;
        }
        #pragma unroll
        for (int it = 0; it < B_IT; it++) {
            int id = tid + it*THREADS;
            int r  = id / (BK/4);
            int c4 = id % (BK/4);
            float4 v = *reinterpret_cast<const float4*>(B + (size_t)(bn + r)*Bld + k0 + c4*4);
            Bs[c4*4+0][r] = v.x; Bs[c4*4+1][r] = v.y;
            Bs[c4*4+2][r] = v.z; Bs[c4*4+3][r] = v.w;
        }
        __syncthreads();

        #pragma unroll
        for (int k = 0; k < BK; k++) {
            float ra[TM], rb[TN];
            #pragma unroll
            for (int i = 0; i < TM; i += 4) {
                if (TM >= 4) {
                    float4 v = *reinterpret_cast<const float4*>(&As[k][ty*TM + i]);
                    ra[i]=v.x; ra[i+1]=v.y; ra[i+2]=v.z; ra[i+3]=v.w;
                } else {
                    #pragma unroll
                    for (int u = 0; u < TM; u++) ra[u] = As[k][ty*TM + u];
                }
            }
            #pragma unroll
            for (int j = 0; j < TN; j += 4) {
                if (TN >= 4) {
                    float4 v = *reinterpret_cast<const float4*>(&Bs[k][tx*TN + j]);
                    rb[j]=v.x; rb[j+1]=v.y; rb[j+2]=v.z; rb[j+3]=v.w;
                } else {
                    #pragma unroll
                    for (int u = 0; u < TN; u++) rb[u] = Bs[k][tx*TN + u];
                }
            }
            #pragma unroll
            for (int i = 0; i < TM; i++)
                #pragma unroll
                for (int j = 0; j < TN; j++)
                    acc[i][j] = fmaf(ra[i], rb[j], acc[i][j]);
        }
        __syncthreads();
    }

    #pragma unroll
    for (int i = 0; i < TM; i++) {
        int row = bm + ty*TM + i;
        if (row >= M) continue;
        #pragma unroll
        for (int j = 0; j < TN; j++) {
            int col = bn + tx*TN + j;
            C[(size_t)row*Nc + col] = acc[i][j] + bias[col];
        }
    }
}

// ======================================================================================
// HMMA fp16 2-way-split (3 products) GEMM — round-12 configuration (FROZEN).
// A split on the fly into SMEM; B pre-split fragments staged GLOBAL -> regs -> SMEM.
// ======================================================================================
__device__ __forceinline__ void split4(float4 v, unsigned& h0, unsigned& h1,
                                       unsigned& l0, unsigned& l1) {
    __half hx = __float2half_rn(v.x), hy = __float2half_rn(v.y);
    __half hz = __float2half_rn(v.z), hw = __float2half_rn(v.w);
    __half2 H0 = __halves2half2(hx, hy), H1 = __halves2half2(hz, hw);
    float lx = v.x - __half2float(hx), ly = v.y - __half2float(hy);
    float lz = v.z - __half2float(hz), lw = v.w - __half2float(hw);
    __half2 L0 = __floats2half2_rn(lx, ly), L1 = __floats2half2_rn(lz, lw);
    h0 = *reinterpret_cast<unsigned*>(&H0); h1 = *reinterpret_cast<unsigned*>(&H1);
    l0 = *reinterpret_cast<unsigned*>(&L0); l1 = *reinterpret_cast<unsigned*>(&L1);
}

__device__ __forceinline__ void mma16816(float* d, const unsigned* a, const unsigned* b) {
    asm("mma.sync.aligned.m16n8k16.row.col.f32.f16.f16.f32 "
        "{%0,%1,%2,%3}, {%4,%5,%6,%7}, {%8,%9}, {%0,%1,%2,%3};"
        : "+f"(d[0]), "+f"(d[1]), "+f"(d[2]), "+f"(d[3])
        : "r"(a[0]), "r"(a[1]), "r"(a[2]), "r"(a[3]), "r"(b[0]), "r"(b[1]));
}

// AMODE: 0 plain / 1 vnode-substitute tail.  SMODE: 0 / 1 split C,C2.
// EMODE: 0 += bias[col] / 1 += rowT[map[row]*512 + col].
template<int BN, int AMODE, int SMODE, int EMODE>
__global__ void __launch_bounds__(256, 1) hgemm_k(
    const float* __restrict__ A, const float* __restrict__ A2, const int* __restrict__ map,
    const uint2* __restrict__ Bhg, const uint2* __restrict__ Blg,
    const float* __restrict__ bias, const float* __restrict__ rowT,
    float* __restrict__ C, float* __restrict__ C2,
    int M, int Nc, int K, int Nsplit)
{
    extern __shared__ char sm[];
    constexpr int NT = 4;
    constexpr int WN = BN / 32;
    constexpr int WM = 8 / WN;
    constexpr int MT = 128 / (WM * 16);
    constexpr int ASZ = 8192;
    constexpr int BOFF = 2 * ASZ;
    constexpr int BSZ = BN * 64;
    constexpr int STAGE = 2 * ASZ + 2 * BSZ;
    constexpr int B_IT = BN / 32;

    const int tid = threadIdx.x;
    const int wid = tid >> 5, lane = tid & 31;
    const int grp = lane >> 2, tig = lane & 3;
    const int bm = blockIdx.y * 128, bn = blockIdx.x * BN;
    const int wm = wid / WN, wn = wid % WN;
    const int KC = K >> 5;
    const int ntg_cta0 = bn >> 3;

    float acc[MT][NT][4];
    #pragma unroll
    for (int i = 0; i < MT; i++)
        #pragma unroll
        for (int j = 0; j < NT; j++)
            #pragma unroll
            for (int q = 0; q < 4; q++) acc[i][j][q] = 0.f;

    float4 ra[4];
    uint2 rbh[B_IT], rbl[B_IT];

    auto loadA = [&](int k0) {
        #pragma unroll
        for (int it = 0; it < 4; it++) {
            int id = tid + it * 256;
            int r = id >> 3, q = id & 7;
            int rr = bm + r; if (rr >= M) rr = M - 1;
            int gk = k0 + q * 4;
            const float* p;
            if (AMODE == 0) p = A + (size_t)rr * K + gk;
            else            p = ((rr < Nsplit) ? A + (size_t)rr * K
                                               : A2 + (size_t)(rr - Nsplit) * K) + gk;
            ra[it] = *reinterpret_cast<const float4*>(p);
        }
    };

    auto loadB = [&](int c) {
        #pragma unroll
        for (int it = 0; it < B_IT; it++) {
            int l = tid + it * 256;
            int ntg_local = l >> 6, rem = l & 63;
            int gidx = ((ntg_cta0 + ntg_local) * KC + c) * 64 + rem;
            rbh[it] = __ldg(Bhg + gidx);
            rbl[it] = __ldg(Blg + gidx);
        }
    };

    auto storeStage = [&](char* stg) {
        #pragma unroll
        for (int it = 0; it < 4; it++) {
            int id = tid + it * 256;
            int r = id >> 3, q = id & 7;
            int kc = q * 4, ks = kc >> 4, kcw = kc & 15;
            int mt = r >> 4;
            int lane0 = (r & 7) * 4 + ((kcw & 7) >> 1);
            int reg = ((r >> 3) & 1) + ((kcw >> 3) << 1);
            unsigned h0, h1, l0, l1; split4(ra[it], h0, h1, l0, l1);
            unsigned off = ((ks * 8 + mt) * 32 + lane0) * 16 + reg * 4;
            *reinterpret_cast<unsigned*>(stg + off) = h0;
            *reinterpret_cast<unsigned*>(stg + off + 16) = h1;
            *reinterpret_cast<unsigned*>(stg + ASZ + off) = l0;
            *reinterpret_cast<unsigned*>(stg + ASZ + off + 16) = l1;
        }
        #pragma unroll
        for (int it = 0; it < B_IT; it++) {
            int l = tid + it * 256;
            *reinterpret_cast<uint2*>(stg + BOFF + l * 8) = rbh[it];
            *reinterpret_cast<uint2*>(stg + BOFF + BSZ + l * 8) = rbl[it];
        }
    };

    loadA(0); loadB(0);
    storeStage(sm);
    __syncthreads();

    const int NCH = KC;
    for (int i = 0; i < NCH; i++) {
        if (i + 1 < NCH) { loadA((i + 1) * 32); loadB(i + 1); }
        char* stg = sm + (i & 1) * STAGE;
        #pragma unroll
        for (int ks = 0; ks < 2; ks++) {
            unsigned Ah[MT][4], Al[MT][4], Bh[NT][2], Bl[NT][2];
            #pragma unroll
            for (int t = 0; t < NT; t++) {
                int l = (wn * NT + t) * 64 + ks * 32 + lane;
                uint2 h = *reinterpret_cast<const uint2*>(stg + BOFF + l * 8);
                uint2 lo = *reinterpret_cast<const uint2*>(stg + BOFF + BSZ + l * 8);
                Bh[t][0] = h.x; Bh[t][1] = h.y;
                Bl[t][0] = lo.x; Bl[t][1] = lo.y;
            }
            #pragma unroll
            for (int t = 0; t < MT; t++) {
                int mt = wm * MT + t;
                unsigned off = ((ks * 8 + mt) * 32 + lane) * 16;
                uint4 h = *reinterpret_cast<const uint4*>(stg + off);
                uint4 l = *reinterpret_cast<const uint4*>(stg + ASZ + off);
                Ah[t][0] = h.x; Ah[t][1] = h.y; Ah[t][2] = h.z; Ah[t][3] = h.w;
                Al[t][0] = l.x; Al[t][1] = l.y; Al[t][2] = l.z; Al[t][3] = l.w;
            }
            #pragma unroll
            for (int ti = 0; ti < MT; ti++)
                #pragma unroll
                for (int tj = 0; tj < NT; tj++) {
                    mma16816(acc[ti][tj], Ah[ti], Bh[tj]);
                    mma16816(acc[ti][tj], Ah[ti], Bl[tj]);
                    mma16816(acc[ti][tj], Al[ti], Bh[tj]);
                }
        }
        if (i + 1 < NCH) {
            storeStage(sm + ((i + 1) & 1) * STAGE);
            __syncthreads();
        }
    }

    #pragma unroll
    for (int i = 0; i < MT; i++) {
        #pragma unroll
        for (int j = 0; j < NT; j++) {
            int col = bn + (wn * NT + j) * 8 + tig * 2;
            float bx = 0.f, by = 0.f;
            if (EMODE == 0) { bx = bias[col]; by = bias[col + 1]; }
            int row0 = bm + (wm * MT + i) * 16 + grp;
            #pragma unroll
            for (int h = 0; h < 2; h++) {
                int row = row0 + h * 8;
                if (row >= M) continue;
                float ax = acc[i][j][h * 2 + 0];
                float ay = acc[i][j][h * 2 + 1];
                float2 v;
                if (EMODE == 1) {
                    const float* tb = rowT + (size_t)map[row] * DD + col;
                    v = make_float2(ax + tb[0], ay + tb[1]);
                } else {
                    v = make_float2(ax + bx, ay + by);
                }
                if (SMODE == 0 || row < Nsplit) {
                    *reinterpret_cast<float2*>(C + (size_t)row * Nc + col) = v;
                } else {
                    float* p = C2 + (size_t)(row - Nsplit) * Nc + col;
                    p[0] = v.x; p[1] = v.y;
                }
            }
        }
    }
}

// ---------------- fused LayerNorm + ELU (+ optional tail bias), warp/row ----------------
__global__ void ln_elu_k(const float* __restrict__ in, float* __restrict__ out,
                         const float* __restrict__ g, const float* __restrict__ beta,
                         const float* __restrict__ tail_bias, int M, int Ntail0)
{
    int w = (blockIdx.x * blockDim.x + threadIdx.x) >> 5;
    int lane = threadIdx.x & 31;
    if (w >= M) return;
    const float* row = in + (size_t)w * DD;
    float4 v[4];
    float s = 0.f, sq = 0.f;
    #pragma unroll
    for (int q = 0; q < 4; q++) {
        v[q] = *reinterpret_cast<const float4*>(row + q * 128 + lane * 4);
        s  += v[q].x + v[q].y + v[q].z + v[q].w;
        sq += v[q].x * v[q].x + v[q].y * v[q].y + v[q].z * v[q].z + v[q].w * v[q].w;
    }
    #pragma unroll
    for (int o = 16; o; o >>= 1) {
        s  += __shfl_xor_sync(0xffffffffu, s,  o);
        sq += __shfl_xor_sync(0xffffffffu, sq, o);
    }
    float mean = s * (1.f / 512.f);
    float var  = sq * (1.f / 512.f) - mean * mean;
    float inv  = rsqrtf(var + 1e-5f);
    float* orow = out + (size_t)w * DD;
    bool tail = (tail_bias != nullptr) && (w >= Ntail0);
    #pragma unroll
    for (int q = 0; q < 4; q++) {
        int c = q * 128 + lane * 4;
        float4 gv = *reinterpret_cast<const float4*>(g + c);
        float4 bv = *reinterpret_cast<const float4*>(beta + c);
        float4 o;
        o.x = elu1((v[q].x - mean) * inv * gv.x + bv.x);
        o.y = elu1((v[q].y - mean) * inv * gv.y + bv.y);
        o.z = elu1((v[q].z - mean) * inv * gv.z + bv.z);
        o.w = elu1((v[q].w - mean) * inv * gv.w + bv.w);
        if (tail) {
            float4 tb = *reinterpret_cast<const float4*>(tail_bias + (size_t)(w - Ntail0) * DD + c);
            o.x += tb.x; o.y += tb.y; o.z += tb.z; o.w += tb.w;
        }
        *reinterpret_cast<float4*>(orow + c) = o;
    }
}

// ---------------- exact LN+ELU on compact rows (verbatim ln_elu arithmetic) --------------
__global__ void ln_fix_k(const float* __restrict__ in, float* __restrict__ out,
                         const float* __restrict__ g, const float* __restrict__ beta,
                         const float* __restrict__ tb, const int* __restrict__ cntp, int nfix)
{
    int n = cntp ? *cntp : nfix;
    if (n > FCAP) n = FCAP;
    int nw = (gridDim.x * blockDim.x) >> 5;
    int gw = (blockIdx.x * blockDim.x + threadIdx.x) >> 5;
    int lane = threadIdx.x & 31;
    for (int w = gw; w < n; w += nw) {
        const float* row = in + (size_t)w * DD;
        float4 v[4];
        float s = 0.f, sq = 0.f;
        #pragma unroll
        for (int q = 0; q < 4; q++) {
            v[q] = *reinterpret_cast<const float4*>(row + q * 128 + lane * 4);
            s  += v[q].x + v[q].y + v[q].z + v[q].w;
            sq += v[q].x * v[q].x + v[q].y * v[q].y + v[q].z * v[q].z + v[q].w * v[q].w;
        }
        #pragma unroll
        for (int o = 16; o; o >>= 1) {
            s  += __shfl_xor_sync(0xffffffffu, s,  o);
            sq += __shfl_xor_sync(0xffffffffu, sq, o);
        }
        float mean = s * (1.f / 512.f);
        float var  = sq * (1.f / 512.f) - mean * mean;
        float inv  = rsqrtf(var + 1e-5f);
        float* orow = out + (size_t)w * DD;
        bool tail = (tb != nullptr);
        #pragma unroll
        for (int q = 0; q < 4; q++) {
            int c = q * 128 + lane * 4;
            float4 gv = *reinterpret_cast<const float4*>(g + c);
            float4 bv = *reinterpret_cast<const float4*>(beta + c);
            float4 o;
            o.x = elu1((v[q].x - mean) * inv * gv.x + bv.x);
            o.y = elu1((v[q].y - mean) * inv * gv.y + bv.y);
            o.z = elu1((v[q].z - mean) * inv * gv.z + bv.z);
            o.w = elu1((v[q].w - mean) * inv * gv.w + bv.w);
            if (tail) {
                float4 t = *reinterpret_cast<const float4*>(tb + (size_t)w * DD + c);
                o.x += t.x; o.y += t.y; o.z += t.z; o.w += t.w;
            }
            *reinterpret_cast<float4*>(orow + c) = o;
        }
    }
}

// ---------------- dst[64,64] = h_tail @ Wd^T + bd + attn_bias, transposed ---------------
__global__ void dst_k(const float* __restrict__ h_tail, const float* __restrict__ Wd,
                      const float* __restrict__ bd, const float* __restrict__ ab,
                      float* __restrict__ dstT)
{
    int idx = blockIdx.x * blockDim.x + threadIdx.x;
    if (idx >= 64 * 64) return;
    int j = idx >> 6;
    int a = idx & 63;
    const float* hr = h_tail + (size_t)j * DD;
    const float* wr = Wd + (size_t)a * DD;
    float s = 0.f;
    for (int d = 0; d < DD; d += 4) {
        float4 hv = *reinterpret_cast<const float4*>(hr + d);
        float4 wv = *reinterpret_cast<const float4*>(wr + d);
        s = fmaf(hv.x, wv.x, s); s = fmaf(hv.y, wv.y, s);
        s = fmaf(hv.z, wv.z, s); s = fmaf(hv.w, wv.w, s);
    }
    s += bd[a] + ab[j * 64 + a];
    dstT[a * 64 + j] = s;
}

// ---------------- argmax + ambiguity flagging ----------------
__global__ void argmax_flag_k(const float* __restrict__ src, const float* __restrict__ dstT,
                              int* __restrict__ cmap, float* __restrict__ map_out,
                              int* __restrict__ list, int* __restrict__ cnt, int Nrows)
{
    __shared__ float sdT[64 * 64];
    __shared__ float ssrc[8][64];
    int tid = threadIdx.x;
    for (int i = tid; i < 64 * 64; i += blockDim.x) sdT[i] = dstT[i];
    __syncthreads();
    int warp = tid >> 5, lane = tid & 31;
    int row0 = blockIdx.x * 64;
    for (int r = warp; r < 64; r += 8) {
        int row = row0 + r;
        if (row >= Nrows) break;
        ssrc[warp][lane]      = src[(size_t)row * 64 + lane];
        ssrc[warp][lane + 32] = src[(size_t)row * 64 + lane + 32];
        __syncwarp();
        float a = 0.f, b = 0.f;
        #pragma unroll
        for (int k = 0; k < 64; k++) {
            float sv = ssrc[warp][k];
            a = fmaf(sv, sdT[k * 64 + lane],      a);
            b = fmaf(sv, sdT[k * 64 + lane + 32], b);
        }
        float v1, v2; int i1;
        if (b > a) { v1 = b; i1 = lane + 32; v2 = a; }
        else       { v1 = a; i1 = lane;      v2 = b; }
        #pragma unroll
        for (int o = 16; o; o >>= 1) {
            float ov1 = __shfl_xor_sync(0xffffffffu, v1, o);
            int   oi1 = __shfl_xor_sync(0xffffffffu, i1, o);
            float ov2 = __shfl_xor_sync(0xffffffffu, v2, o);
            if (ov1 > v1 || (ov1 == v1 && oi1 < i1)) {
                v2 = fmaxf(v1, ov2); v1 = ov1; i1 = oi1;
            } else {
                v2 = fmaxf(ov1, v2);
            }
        }
        if (lane == 0) {
            cmap[row] = i1; map_out[row] = (float)i1;
            if (v1 - v2 < 1e-4f * (1.f + fabsf(v1))) {
                int ix = atomicAdd(cnt, 1);
                if (ix < FCAP) list[ix] = row;
            }
        }
        __syncwarp();
    }
}

// ---------------- gather flagged x rows into compact buffer ----------------
__global__ void gather_k(const float* __restrict__ x, const int* __restrict__ list,
                         const int* __restrict__ cntp, float* __restrict__ out)
{
    int n = *cntp; if (n > FCAP) n = FCAP;
    for (int i = blockIdx.x; i < n; i += gridDim.x) {
        int row = list[i];
        const float4* s = reinterpret_cast<const float4*>(x + (size_t)row * DD);
        float4* d = reinterpret_cast<float4*>(out + (size_t)i * DD);
        for (int k = threadIdx.x; k < DD / 4; k += blockDim.x) d[k] = s[k];
    }
}

// ---------------- exact rescore + argmax for flagged rows ----------------
__global__ void rescore_k(const float* __restrict__ h2, const float* __restrict__ Ws,
                          const float* __restrict__ bs, const float* __restrict__ dstT,
                          const int* __restrict__ list, const int* __restrict__ cntp,
                          int* __restrict__ cmap, float* __restrict__ map_out)
{
    __shared__ float sdT[64 * 64];
    __shared__ float ssrc[8][64];
    int tid = threadIdx.x;
    for (int i = tid; i < 64 * 64; i += blockDim.x) sdT[i] = dstT[i];
    __syncthreads();
    int warp = tid >> 5, lane = tid & 31;
    int n = *cntp; if (n > FCAP) n = FCAP;
    int nw = gridDim.x * 8;
    for (int i = blockIdx.x * 8 + warp; i < n; i += nw) {
        const float4* hr = reinterpret_cast<const float4*>(h2 + (size_t)i * DD);
        #pragma unroll
        for (int half = 0; half < 2; half++) {
            int a = lane + half * 32;
            const float4* w = reinterpret_cast<const float4*>(Ws + (size_t)a * DD);
            float acc = 0.f;
            for (int k = 0; k < DD / 4; k++) {
                float4 h = hr[k]; float4 ww = w[k];
                acc = fmaf(h.x, ww.x, acc); acc = fmaf(h.y, ww.y, acc);
                acc = fmaf(h.z, ww.z, acc); acc = fmaf(h.w, ww.w, acc);
            }
            ssrc[warp][a] = acc + bs[a];
        }
        __syncwarp();
        float a = 0.f, b = 0.f;
        #pragma unroll
        for (int k = 0; k < 64; k++) {
            float sv = ssrc[warp][k];
            a = fmaf(sv, sdT[k * 64 + lane],      a);
            b = fmaf(sv, sdT[k * 64 + lane + 32], b);
        }
        float bv; int bi;
        if (b > a) { bv = b; bi = lane + 32; } else { bv = a; bi = lane; }
        #pragma unroll
        for (int o = 16; o; o >>= 1) {
            float ov = __shfl_xor_sync(0xffffffffu, bv, o);
            int   oi = __shfl_xor_sync(0xffffffffu, bi, o);
            if (ov > bv || (ov == bv && oi < bi)) { bv = ov; bi = oi; }
        }
        if (lane == 0) { int row = list[i]; cmap[row] = bi; map_out[row] = (float)bi; }
        __syncwarp();
    }
}

// ---------------- misc ----------------
__global__ void tail_setup_k(float* __restrict__ h, const float* __restrict__ vbd,
                             int* __restrict__ cmap, float* __restrict__ lossp, int Ntail0)
{
    int idx = blockIdx.x * blockDim.x + threadIdx.x;
    if (idx < PV * DD) h[(size_t)Ntail0 * DD + idx] += vbd[idx];
    if (idx < PV) cmap[Ntail0 + idx] = idx;
    if (idx == 0) *lossp = 0.f;
}

extern "C" void kernel_launch(void* const* d_in, const int* in_sizes, int n_in,
                              void* d_out, int out_size)
{
    const float* x    = (const float*)d_in[0];
    const float* vemb = (const float*)d_in[1];
    const float* vbh  = (const float*)d_in[2];
    const float* vbd  = (const float*)d_in[3];
    const float* Win  = (const float*)d_in[4];
    const float* bin  = (const float*)d_in[5];
    const float* ghid = (const float*)d_in[6];
    const float* bhid = (const float*)d_in[7];
    const float* Wenc = (const float*)d_in[8];
    const float* benc = (const float*)d_in[9];
    const float* gdcd = (const float*)d_in[10];
    const float* bdcd = (const float*)d_in[11];
    const float* Ws   = (const float*)d_in[12];
    const float* bs   = (const float*)d_in[13];
    const float* Wd   = (const float*)d_in[14];
    const float* bd   = (const float*)d_in[15];
    const float* ab   = (const float*)d_in[16];
    const float* Wag  = (const float*)d_in[17];
    const float* bag  = (const float*)d_in[18];
    const float* Wout = (const float*)d_in[19];
    const float* bout = (const float*)d_in[20];

    const int M = in_sizes[0] / DD;
    const int N = M - PV;

    float *bufA, *bufB, *srcb, *dstT, *tail1, *tail2; int *cmap, *list, *cnt;
    uint2 *Winh, *Winl, *Wench, *Wencl, *Wagh, *Wagl, *Wouth, *Woutl, *Wsh, *Wsl;
    cudaGetSymbolAddress((void**)&bufA, g_bufA);
    cudaGetSymbolAddress((void**)&bufB, g_bufB);
    cudaGetSymbolAddress((void**)&srcb, g_srcb);
    cudaGetSymbolAddress((void**)&dstT, g_dstT);
    cudaGetSymbolAddress((void**)&tail1, g_tail1);
    cudaGetSymbolAddress((void**)&tail2, g_tail2);
    cudaGetSymbolAddress((void**)&cmap, g_cmap);
    cudaGetSymbolAddress((void**)&list, g_list);
    cudaGetSymbolAddress((void**)&cnt, g_cnt);
    cudaGetSymbolAddress((void**)&Winh, g_Winh);   cudaGetSymbolAddress((void**)&Winl, g_Winl);
    cudaGetSymbolAddress((void**)&Wench, g_Wench); cudaGetSymbolAddress((void**)&Wencl, g_Wencl);
    cudaGetSymbolAddress((void**)&Wagh, g_Wagh);   cudaGetSymbolAddress((void**)&Wagl, g_Wagl);
    cudaGetSymbolAddress((void**)&Wouth, g_Wouth); cudaGetSymbolAddress((void**)&Woutl, g_Woutl);
    cudaGetSymbolAddress((void**)&Wsh, g_Wsh);     cudaGetSymbolAddress((void**)&Wsl, g_Wsl);

    float* out   = (float*)d_out;
    float* lossp = out + (size_t)N * DD;
    float* reps  = lossp + 1;
    float* mapo  = reps + (size_t)PV * DD;

    float* xg = bufA;
    float* t1 = bufA + (size_t)FCAP * DD;
    float* t2 = bufA;
    float* Tb = tail1;   // T table (64 x 512)

    constexpr int SMH   = 2 * (2 * 8192 + 2 * 128 * 64);  // 65536 (BN=128)
    constexpr int SMH64 = 2 * (2 * 8192 + 2 * 64 * 64);   // 49152 (BN=64)
    cudaFuncSetAttribute(hgemm_k<128,1,0,0>, cudaFuncAttributeMaxDynamicSharedMemorySize, SMH);
    cudaFuncSetAttribute(hgemm_k<128,0,0,0>, cudaFuncAttributeMaxDynamicSharedMemorySize, SMH);
    cudaFuncSetAttribute(hgemm_k<128,0,0,1>, cudaFuncAttributeMaxDynamicSharedMemorySize, SMH);
    cudaFuncSetAttribute(hgemm_k<128,0,1,0>, cudaFuncAttributeMaxDynamicSharedMemorySize, SMH);
    cudaFuncSetAttribute(hgemm_k<64,0,0,0>,  cudaFuncAttributeMaxDynamicSharedMemorySize, SMH64);

    const int gm = (M + 127) / 128;
    const dim3 gfix(8, (FCAP + 63) / 64);
    dim3 blk(256);

    // ---- all weight pre-splits + cnt reset in ONE launch ----
    presplit_all_k<<<(270337 + 255) / 256, 256>>>(Win, Wenc, Wag, Wout, Ws);

    // ---- GEMM1 (HMMA) + LN ; exact tail h1 (32x32 tile, bit-identical chain) ----
    hgemm_k<128,1,0,0><<<dim3(DD/128, gm), blk, SMH>>>(x, vemb, nullptr, Winh, Winl, bin, nullptr, bufA, nullptr, M, DD, DD, N);
    ln_elu_k<<<(M + 7) / 8, 256>>>(bufA, bufB, ghid, bhid, vbh, M, N);
    sgemm_k<32,32,64,2,2><<<dim3(16, 2), blk>>>(vemb, Win, bin, tail1, PV, DD, DD, nullptr, DD);
    ln_fix_k<<<8, 256>>>(tail1, bufB + (size_t)N * DD, ghid, bhid, vbh, nullptr, PV);

    // ---- GEMM2 (HMMA) + LN ; exact tail h2 ----
    hgemm_k<128,0,0,0><<<dim3(DD/128, gm), blk, SMH>>>(bufB, nullptr, nullptr, Wench, Wencl, benc, nullptr, bufA, nullptr, M, DD, DD, N);
    sgemm_k<32,32,64,2,2><<<dim3(16, 2), blk>>>(bufB + (size_t)N * DD, Wenc, benc, tail2, PV, DD, DD, nullptr, DD);
    ln_elu_k<<<(M + 7) / 8, 256>>>(bufA, bufB, gdcd, bdcd, nullptr, M, N);
    ln_fix_k<<<8, 256>>>(tail2, bufB + (size_t)N * DD, gdcd, bdcd, nullptr, nullptr, PV);

    // ---- src (HMMA) ; dst (exact) ; argmax+flag ----
    hgemm_k<64,0,0,0><<<dim3(1, (N + 127) / 128), blk, SMH64>>>(bufB, nullptr, nullptr, Wsh, Wsl, bs, nullptr, srcb, nullptr, N, 64, DD, N);
    dst_k<<<16, 256>>>(bufB + (size_t)N * DD, Wd, bd, ab, dstT);
    argmax_flag_k<<<(N + 63) / 64, 256>>>(srcb, dstT, cmap, mapo, list, cnt, N);

    // ---- exact repair of flagged rows ----
    gather_k<<<2048, 128>>>(x, list, cnt, xg);
    sgemm_k<64,64,64,4,4><<<gfix, blk>>>(xg, Win, bin, t1, 0, DD, DD, cnt, DD);
    ln_fix_k<<<512, 256>>>(t1, t1, ghid, bhid, nullptr, cnt, 0);
    sgemm_k<64,64,64,4,4><<<gfix, blk>>>(t1, Wenc, benc, t2, 0, DD, DD, cnt, DD);
    ln_fix_k<<<512, 256>>>(t2, t2, gdcd, bdcd, nullptr, cnt, 0);
    rescore_k<<<256, 256>>>(t2, Ws, bs, dstT, list, cnt, cmap, mapo);

    // ---- tail fixups ----
    tail_setup_k<<<(PV * DD + 255) / 256, 256>>>(bufB, vbd, cmap, lossp, N);

    // ---- T table: T[j] = h_tail'[j] @ WagRight^T + bag ----
    sgemm_k<32,32,64,2,2><<<dim3(16, 2), blk>>>(bufB + (size_t)N * DD, Wag + 512, bag, Tb, PV, DD, DD, nullptr, 2*DD);

    // ---- aggr (HMMA, K=512 + per-row T epilogue) ; LN ; out (HMMA, split store) ----
    hgemm_k<128,0,0,1><<<dim3(DD/128, gm), blk, SMH>>>(bufB, nullptr, cmap, Wagh, Wagl, bag, Tb, bufA, nullptr, M, DD, DD, N);
    ln_elu_k<<<(M + 7) / 8, 256>>>(bufA, bufB, gdcd, bdcd, nullptr, M, N);
    hgemm_k<128,0,1,0><<<dim3(DD/128, gm), blk, SMH>>>(bufB, nullptr, nullptr, Wouth, Woutl, bout, nullptr, out, reps, M, DD, DD, N);
}